// round 2
// baseline (speedup 1.0000x reference)
#include <cuda_runtime.h>
#include <cstdint>

// ScorePredictor: score[e] = dot(x[src[e]], x[dst[e]])
// x: [N, 64] fp32 (identified by element count), src/dst: [E] int32 OR int64.
// 16 lanes per edge: each lane loads one float4 from each row (16*16B = 256B
// = full row, perfectly coalesced). Shuffle reduce within the 16-lane group.

static constexpr int LANES_PER_EDGE = 16;
static constexpr int THREADS = 256;
static constexpr int D_FEAT = 64;

__device__ int g_idx_is_64 = 0;

// Detect whether index arrays are int64 or int32.
// If int64 with values < 2^31, memory layout (LE) is [lo,0,lo,0,...]:
// all odd 32-bit words are zero. For random int32 indices in [0,1e5) the
// chance all 32 odd words are zero is ~(1e-5)^32 — effectively impossible.
__global__ void detect_dtype_kernel(const unsigned int* __restrict__ idx_words)
{
    if (threadIdx.x == 0 && blockIdx.x == 0) {
        int is64 = 1;
        #pragma unroll
        for (int i = 0; i < 32; i++) {
            if (idx_words[2 * i + 1] != 0u) { is64 = 0; break; }
        }
        g_idx_is_64 = is64;
    }
}

__global__ __launch_bounds__(THREADS)
void edge_dot_kernel(const float4* __restrict__ x4,
                     const void* __restrict__ src_raw,
                     const void* __restrict__ dst_raw,
                     float* __restrict__ out,
                     int n_edges,
                     int n_nodes)
{
    int tid  = blockIdx.x * THREADS + threadIdx.x;
    int e    = tid >> 4;
    int lane = tid & 15;
    if (e >= n_edges) return;

    long long s, d;
    if (g_idx_is_64) {
        s = ((const long long*)src_raw)[e];
        d = ((const long long*)dst_raw)[e];
    } else {
        s = (long long)((const int*)src_raw)[e];
        d = (long long)((const int*)dst_raw)[e];
    }
    // Clamp: wrong-dtype guess degrades to wrong values, not a crash.
    if (s < 0) s = 0; if (s >= n_nodes) s = n_nodes - 1;
    if (d < 0) d = 0; if (d >= n_nodes) d = n_nodes - 1;

    const float4 a = x4[s * LANES_PER_EDGE + lane];
    const float4 b = x4[d * LANES_PER_EDGE + lane];

    float sum = a.x * b.x + a.y * b.y + a.z * b.z + a.w * b.w;

    sum += __shfl_down_sync(0xFFFFFFFFu, sum, 8, 16);
    sum += __shfl_down_sync(0xFFFFFFFFu, sum, 4, 16);
    sum += __shfl_down_sync(0xFFFFFFFFu, sum, 2, 16);
    sum += __shfl_down_sync(0xFFFFFFFFu, sum, 1, 16);

    if (lane == 0) out[e] = sum;
}

extern "C" void kernel_launch(void* const* d_in, const int* in_sizes, int n_in,
                              void* d_out, int out_size)
{
    // Identify x as the largest input (N*64 floats); the other two are indices.
    int xi = 0;
    for (int i = 1; i < n_in; i++)
        if (in_sizes[i] > in_sizes[xi]) xi = i;
    int i1 = -1, i2 = -1;
    for (int i = 0; i < n_in; i++) {
        if (i == xi) continue;
        if (i1 < 0) i1 = i; else i2 = i;
    }

    const float4* x4  = (const float4*)d_in[xi];
    const void*   src = d_in[i1];
    const void*   dst = d_in[i2];
    float*        out = (float*)d_out;

    int n_edges = in_sizes[i1];
    int n_nodes = in_sizes[xi] / D_FEAT;

    detect_dtype_kernel<<<1, 32>>>((const unsigned int*)src);

    long long total_threads = (long long)n_edges * LANES_PER_EDGE;
    int blocks = (int)((total_threads + THREADS - 1) / THREADS);
    edge_dot_kernel<<<blocks, THREADS>>>(x4, src, dst, out, n_edges, n_nodes);
}

// round 3
// speedup vs baseline: 1.6654x; 1.6654x over previous
#include <cuda_runtime.h>
#include <cuda_fp16.h>
#include <cstdint>

// ScorePredictor: score[e] = dot(x[src[e]], x[dst[e]])
// x: [N, 64] fp32, src/dst: [E] int32 or int64 (runtime-detected).
//
// R3: L1-wavefront-bound per ncu (L1=48.9% top pipe). Halve gather bytes by
// caching x as fp16 in __device__ scratch: row = 128B = 1 L1 wavefront.
// 8 lanes/edge, each loads one uint4 (8 halves) per row; fp32 accumulate.

static constexpr int D_FEAT = 64;
static constexpr int MAX_NODES = 262144;              // >= 100000, headroom
static constexpr int THREADS = 256;

__device__ int g_idx_is_64 = 0;
__device__ __align__(16) __half g_xh[(size_t)MAX_NODES * D_FEAT];  // 32MB scratch

// --- dtype detection: int64 little-endian with values < 2^31 has all odd
// 32-bit words zero; random int32 node ids make that impossible. ---
__global__ void detect_dtype_kernel(const unsigned int* __restrict__ idx_words)
{
    if (threadIdx.x == 0) {
        int is64 = 1;
        #pragma unroll
        for (int i = 0; i < 32; i++)
            if (idx_words[2 * i + 1] != 0u) { is64 = 0; break; }
        g_idx_is_64 = is64;
    }
}

// --- fp32 -> fp16 conversion of x into scratch. 4 floats per thread. ---
__global__ __launch_bounds__(THREADS)
void convert_kernel(const float4* __restrict__ x4, int n4)
{
    int i = blockIdx.x * THREADS + threadIdx.x;
    if (i >= n4) return;
    float4 v = x4[i];
    __half2 h0 = __floats2half2_rn(v.x, v.y);
    __half2 h1 = __floats2half2_rn(v.z, v.w);
    uint2 p;
    p.x = *reinterpret_cast<unsigned*>(&h0);
    p.y = *reinterpret_cast<unsigned*>(&h1);
    reinterpret_cast<uint2*>(g_xh)[i] = p;
}

// --- main: 8 lanes per edge, one uint4 (8 halves, 16B) per lane per row. ---
__global__ __launch_bounds__(THREADS)
void edge_dot_kernel(const void* __restrict__ src_raw,
                     const void* __restrict__ dst_raw,
                     float* __restrict__ out,
                     int n_edges)
{
    int tid  = blockIdx.x * THREADS + threadIdx.x;
    int e    = tid >> 3;
    int lane = tid & 7;
    if (e >= n_edges) return;

    unsigned s, d;
    if (g_idx_is_64) {
        s = (unsigned)((const unsigned long long*)src_raw)[e];
        d = (unsigned)((const unsigned long long*)dst_raw)[e];
    } else {
        s = (unsigned)((const unsigned*)src_raw)[e];
        d = (unsigned)((const unsigned*)dst_raw)[e];
    }

    const uint4* xh4 = reinterpret_cast<const uint4*>(g_xh);
    uint4 a = xh4[s * 8u + lane];
    uint4 b = xh4[d * 8u + lane];

    float sum = 0.0f;
    {
        const unsigned* ap = &a.x;
        const unsigned* bp = &b.x;
        #pragma unroll
        for (int j = 0; j < 4; j++) {
            __half2 ha = *reinterpret_cast<const __half2*>(&ap[j]);
            __half2 hb = *reinterpret_cast<const __half2*>(&bp[j]);
            float2 fa = __half22float2(ha);
            float2 fb = __half22float2(hb);
            sum = fmaf(fa.x, fb.x, sum);
            sum = fmaf(fa.y, fb.y, sum);
        }
    }

    // Reduce across the 8-lane group.
    sum += __shfl_down_sync(0xFFFFFFFFu, sum, 4, 8);
    sum += __shfl_down_sync(0xFFFFFFFFu, sum, 2, 8);
    sum += __shfl_down_sync(0xFFFFFFFFu, sum, 1, 8);

    if (lane == 0) out[e] = sum;
}

extern "C" void kernel_launch(void* const* d_in, const int* in_sizes, int n_in,
                              void* d_out, int out_size)
{
    // x = largest input; the other two are index arrays (order irrelevant:
    // the dot product is symmetric in src/dst).
    int xi = 0;
    for (int i = 1; i < n_in; i++)
        if (in_sizes[i] > in_sizes[xi]) xi = i;
    int i1 = -1, i2 = -1;
    for (int i = 0; i < n_in; i++) {
        if (i == xi) continue;
        if (i1 < 0) i1 = i; else i2 = i;
    }

    const float4* x4  = (const float4*)d_in[xi];
    const void*   src = d_in[i1];
    const void*   dst = d_in[i2];
    float*        out = (float*)d_out;

    int n_edges = in_sizes[i1];
    int n4      = in_sizes[xi] / 4;   // float4 count of x

    detect_dtype_kernel<<<1, 32>>>((const unsigned int*)src);
    convert_kernel<<<(n4 + THREADS - 1) / THREADS, THREADS>>>(x4, n4);

    long long total_threads = (long long)n_edges * 8;
    int blocks = (int)((total_threads + THREADS - 1) / THREADS);
    edge_dot_kernel<<<blocks, THREADS>>>(src, dst, out, n_edges);
}

// round 4
// speedup vs baseline: 2.0588x; 1.2362x over previous
#include <cuda_runtime.h>
#include <cuda_fp16.h>
#include <cstdint>

// ScorePredictor: score[e] = dot(x[src[e]], x[dst[e]])
// x: [N, 64] fp32, src/dst: [E] int32 or int64 (runtime-detected).
//
// R4: merge dtype detection into convert kernel (kill 3.9us launch);
// main kernel processes 2 edges per 8-lane group (4 independent 16B gathers
// per thread) to hide the ~250cyc L2-hit latency on random gathers.

static constexpr int D_FEAT = 64;
static constexpr int MAX_NODES = 262144;
static constexpr int THREADS = 256;

__device__ int g_idx_is_64 = 0;
__device__ __align__(16) __half g_xh[(size_t)MAX_NODES * D_FEAT];  // 32MB scratch

// --- fp32 -> fp16 conversion + dtype detection (block 0 thread 0). ---
__global__ __launch_bounds__(THREADS)
void convert_kernel(const float4* __restrict__ x4, int n4,
                    const unsigned int* __restrict__ idx_words)
{
    int i = blockIdx.x * THREADS + threadIdx.x;
    if (i == 0) {
        // int64 (LE, values < 2^31) => all odd 32-bit words zero.
        int is64 = 1;
        #pragma unroll
        for (int k = 0; k < 32; k++)
            if (idx_words[2 * k + 1] != 0u) { is64 = 0; break; }
        g_idx_is_64 = is64;
    }
    if (i >= n4) return;
    float4 v = x4[i];
    __half2 h0 = __floats2half2_rn(v.x, v.y);
    __half2 h1 = __floats2half2_rn(v.z, v.w);
    uint2 p;
    p.x = *reinterpret_cast<unsigned*>(&h0);
    p.y = *reinterpret_cast<unsigned*>(&h1);
    reinterpret_cast<uint2*>(g_xh)[i] = p;
}

// --- main: 8-lane group handles 2 consecutive edges; 4 gathers in flight. ---
__global__ __launch_bounds__(THREADS)
void edge_dot_kernel(const void* __restrict__ src_raw,
                     const void* __restrict__ dst_raw,
                     float* __restrict__ out,
                     int n_edges)
{
    int tid  = blockIdx.x * THREADS + threadIdx.x;
    int g    = tid >> 3;               // group id
    int lane = tid & 7;
    int e0   = g * 2;
    int e1   = e0 + 1;
    if (e0 >= n_edges) return;
    bool has1 = (e1 < n_edges);
    int e1c = has1 ? e1 : e0;

    unsigned s0, d0, s1, d1;
    if (g_idx_is_64) {
        const unsigned long long* sp = (const unsigned long long*)src_raw;
        const unsigned long long* dp = (const unsigned long long*)dst_raw;
        s0 = (unsigned)sp[e0]; d0 = (unsigned)dp[e0];
        s1 = (unsigned)sp[e1c]; d1 = (unsigned)dp[e1c];
    } else {
        const unsigned* sp = (const unsigned*)src_raw;
        const unsigned* dp = (const unsigned*)dst_raw;
        s0 = sp[e0]; d0 = dp[e0];
        s1 = sp[e1c]; d1 = dp[e1c];
    }

    const uint4* xh4 = reinterpret_cast<const uint4*>(g_xh);
    // Issue all four gathers before any consumption -> MLP = 4.
    uint4 a0 = xh4[s0 * 8u + lane];
    uint4 b0 = xh4[d0 * 8u + lane];
    uint4 a1 = xh4[s1 * 8u + lane];
    uint4 b1 = xh4[d1 * 8u + lane];

    auto dot16 = [](const uint4& a, const uint4& b) -> float {
        float sum = 0.0f;
        const unsigned* ap = &a.x;
        const unsigned* bp = &b.x;
        #pragma unroll
        for (int j = 0; j < 4; j++) {
            __half2 ha = *reinterpret_cast<const __half2*>(&ap[j]);
            __half2 hb = *reinterpret_cast<const __half2*>(&bp[j]);
            float2 fa = __half22float2(ha);
            float2 fb = __half22float2(hb);
            sum = fmaf(fa.x, fb.x, sum);
            sum = fmaf(fa.y, fb.y, sum);
        }
        return sum;
    };

    float sum0 = dot16(a0, b0);
    float sum1 = dot16(a1, b1);

    sum0 += __shfl_down_sync(0xFFFFFFFFu, sum0, 4, 8);
    sum1 += __shfl_down_sync(0xFFFFFFFFu, sum1, 4, 8);
    sum0 += __shfl_down_sync(0xFFFFFFFFu, sum0, 2, 8);
    sum1 += __shfl_down_sync(0xFFFFFFFFu, sum1, 2, 8);
    sum0 += __shfl_down_sync(0xFFFFFFFFu, sum0, 1, 8);
    sum1 += __shfl_down_sync(0xFFFFFFFFu, sum1, 1, 8);

    if (lane == 0) {
        out[e0] = sum0;
        if (has1) out[e1] = sum1;
    }
}

extern "C" void kernel_launch(void* const* d_in, const int* in_sizes, int n_in,
                              void* d_out, int out_size)
{
    // x = largest input; other two are index arrays (dot is symmetric).
    int xi = 0;
    for (int i = 1; i < n_in; i++)
        if (in_sizes[i] > in_sizes[xi]) xi = i;
    int i1 = -1, i2 = -1;
    for (int i = 0; i < n_in; i++) {
        if (i == xi) continue;
        if (i1 < 0) i1 = i; else i2 = i;
    }

    const float4* x4  = (const float4*)d_in[xi];
    const void*   src = d_in[i1];
    const void*   dst = d_in[i2];
    float*        out = (float*)d_out;

    int n_edges = in_sizes[i1];
    int n4      = in_sizes[xi] / 4;

    convert_kernel<<<(n4 + THREADS - 1) / THREADS, THREADS>>>(
        x4, n4, (const unsigned int*)src);

    long long groups = (n_edges + 1) / 2;
    long long total_threads = groups * 8;
    int blocks = (int)((total_threads + THREADS - 1) / THREADS);
    edge_dot_kernel<<<blocks, THREADS>>>(src, dst, out, n_edges);
}

// round 5
// speedup vs baseline: 2.2026x; 1.0698x over previous
#include <cuda_runtime.h>
#include <cuda_fp16.h>
#include <cstdint>

// ScorePredictor: score[e] = dot(x[src[e]], x[dst[e]])
// x: [N, 64] fp32, src/dst: [E] int32 or int64 (runtime-detected).
//
// R5: 4 edges per 8-lane group -> 8 independent 16B gathers in flight per
// thread (MLP=8) to hide random-gather L2 latency. fp16 node cache (128B/row
// = 1 L1 wavefront per gather), fp32 accumulate.

static constexpr int D_FEAT = 64;
static constexpr int MAX_NODES = 262144;
static constexpr int THREADS = 256;
static constexpr int EDGES_PER_GROUP = 4;

__device__ int g_idx_is_64 = 0;
__device__ __align__(16) __half g_xh[(size_t)MAX_NODES * D_FEAT];  // 32MB scratch

// --- fp32 -> fp16 conversion + dtype detection (thread 0). ---
__global__ __launch_bounds__(THREADS)
void convert_kernel(const float4* __restrict__ x4, int n4,
                    const unsigned int* __restrict__ idx_words)
{
    int i = blockIdx.x * THREADS + threadIdx.x;
    if (i == 0) {
        // int64 (LE, values < 2^31) => all odd 32-bit words zero.
        int is64 = 1;
        #pragma unroll
        for (int k = 0; k < 32; k++)
            if (idx_words[2 * k + 1] != 0u) { is64 = 0; break; }
        g_idx_is_64 = is64;
    }
    if (i >= n4) return;
    float4 v = x4[i];
    __half2 h0 = __floats2half2_rn(v.x, v.y);
    __half2 h1 = __floats2half2_rn(v.z, v.w);
    uint2 p;
    p.x = *reinterpret_cast<unsigned*>(&h0);
    p.y = *reinterpret_cast<unsigned*>(&h1);
    reinterpret_cast<uint2*>(g_xh)[i] = p;
}

__device__ __forceinline__ float dot16(const uint4& a, const uint4& b)
{
    float sum = 0.0f;
    const unsigned* ap = &a.x;
    const unsigned* bp = &b.x;
    #pragma unroll
    for (int j = 0; j < 4; j++) {
        __half2 ha = *reinterpret_cast<const __half2*>(&ap[j]);
        __half2 hb = *reinterpret_cast<const __half2*>(&bp[j]);
        float2 fa = __half22float2(ha);
        float2 fb = __half22float2(hb);
        sum = fmaf(fa.x, fb.x, sum);
        sum = fmaf(fa.y, fb.y, sum);
    }
    return sum;
}

// --- main: 8-lane group handles 4 consecutive edges; 8 gathers in flight. ---
__global__ __launch_bounds__(THREADS)
void edge_dot_kernel(const void* __restrict__ src_raw,
                     const void* __restrict__ dst_raw,
                     float* __restrict__ out,
                     int n_edges)
{
    int tid  = blockIdx.x * THREADS + threadIdx.x;
    int g    = tid >> 3;
    int lane = tid & 7;
    int ebase = g * EDGES_PER_GROUP;
    if (ebase >= n_edges) return;

    // Load all 8 indices up front (clamped for the tail).
    unsigned s[EDGES_PER_GROUP], d[EDGES_PER_GROUP];
    int elast = n_edges - 1;
    if (g_idx_is_64) {
        const unsigned long long* sp = (const unsigned long long*)src_raw;
        const unsigned long long* dp = (const unsigned long long*)dst_raw;
        #pragma unroll
        for (int k = 0; k < EDGES_PER_GROUP; k++) {
            int e = ebase + k; e = e < elast ? e : elast;
            s[k] = (unsigned)sp[e];
            d[k] = (unsigned)dp[e];
        }
    } else {
        const unsigned* sp = (const unsigned*)src_raw;
        const unsigned* dp = (const unsigned*)dst_raw;
        #pragma unroll
        for (int k = 0; k < EDGES_PER_GROUP; k++) {
            int e = ebase + k; e = e < elast ? e : elast;
            s[k] = sp[e];
            d[k] = dp[e];
        }
    }

    const uint4* xh4 = reinterpret_cast<const uint4*>(g_xh);

    // Issue all 8 gathers before consuming any -> MLP = 8.
    uint4 a[EDGES_PER_GROUP], b[EDGES_PER_GROUP];
    #pragma unroll
    for (int k = 0; k < EDGES_PER_GROUP; k++) {
        a[k] = xh4[s[k] * 8u + lane];
        b[k] = xh4[d[k] * 8u + lane];
    }

    float sum[EDGES_PER_GROUP];
    #pragma unroll
    for (int k = 0; k < EDGES_PER_GROUP; k++)
        sum[k] = dot16(a[k], b[k]);

    // Interleaved shuffle reductions (4 independent chains).
    #pragma unroll
    for (int off = 4; off >= 1; off >>= 1) {
        #pragma unroll
        for (int k = 0; k < EDGES_PER_GROUP; k++)
            sum[k] += __shfl_down_sync(0xFFFFFFFFu, sum[k], off, 8);
    }

    if (lane == 0) {
        #pragma unroll
        for (int k = 0; k < EDGES_PER_GROUP; k++) {
            int e = ebase + k;
            if (e < n_edges) out[e] = sum[k];
        }
    }
}

extern "C" void kernel_launch(void* const* d_in, const int* in_sizes, int n_in,
                              void* d_out, int out_size)
{
    // x = largest input; other two are index arrays (dot is symmetric).
    int xi = 0;
    for (int i = 1; i < n_in; i++)
        if (in_sizes[i] > in_sizes[xi]) xi = i;
    int i1 = -1, i2 = -1;
    for (int i = 0; i < n_in; i++) {
        if (i == xi) continue;
        if (i1 < 0) i1 = i; else i2 = i;
    }

    const float4* x4  = (const float4*)d_in[xi];
    const void*   src = d_in[i1];
    const void*   dst = d_in[i2];
    float*        out = (float*)d_out;

    int n_edges = in_sizes[i1];
    int n4      = in_sizes[xi] / 4;

    convert_kernel<<<(n4 + THREADS - 1) / THREADS, THREADS>>>(
        x4, n4, (const unsigned int*)src);

    long long groups = (n_edges + EDGES_PER_GROUP - 1) / EDGES_PER_GROUP;
    long long total_threads = groups * 8;
    int blocks = (int)((total_threads + THREADS - 1) / THREADS);
    edge_dot_kernel<<<blocks, THREADS>>>(src, dst, out, n_edges);
}